// round 4
// baseline (speedup 1.0000x reference)
#include <cuda_runtime.h>
#include <cuda_fp16.h>
#include <mma.h>

using namespace nvcuda;

#define N_NODES 8192
#define D_IN    512
#define D_OUT   256
#define PN      288   // padded B columns: 256 values + 1 ones-col (Z) + 31 zeros (18 wmma N-tiles)

// ---------------- scratch (static device arrays; no allocation) ----------------
__device__ __half g_in_h[N_NODES * D_IN];     // input as fp16
__device__ __half g_w_h[D_IN * D_OUT];        // weight as fp16
__device__ float  g_Wh[N_NODES * D_OUT];      // Wh fp32
__device__ float  g_s[N_NODES];               // Wh @ a[:256]
__device__ float  g_t[N_NODES];               // Wh @ a[256:]
__device__ __half g_B1[(size_t)N_NODES * PN]; // e^{t_j}      * [Wh | 1 | 0...]
__device__ __half g_B2[(size_t)N_NODES * PN]; // e^{0.2 t_j}  * [Wh | 1 | 0...]

// ---------------- fp32 -> fp16 convert ----------------
__global__ void f2h_kernel(const float* __restrict__ x, __half* __restrict__ y, int n) {
    int i = blockIdx.x * blockDim.x + threadIdx.x;
    int stride = gridDim.x * blockDim.x;
    for (; i < n; i += stride) y[i] = __float2half(x[i]);
}

// ---------------- Wh = input @ weight (wmma fp16, fp32 accum) ----------------
__global__ __launch_bounds__(256) void gemm_wh_kernel() {
    __shared__ __half As[64 * 80];    // 64 rows x 64 k (pad 80)
    __shared__ __half Bs[64 * 272];   // 64 k x 256 n (pad 272)
    int tid  = threadIdx.x;
    int warp = tid >> 5;
    int grow = blockIdx.x * 64;
    int m0 = (warp >> 1) * 16;        // 4 M-tiles
    int n0 = (warp & 1) * 128;        // 2 N halves, 8 tiles each

    wmma::fragment<wmma::accumulator, 16, 16, 16, float> acc[8];
#pragma unroll
    for (int i = 0; i < 8; i++) wmma::fill_fragment(acc[i], 0.0f);

    for (int kc = 0; kc < D_IN; kc += 64) {
        __syncthreads();
        // A chunk: 64x64 halves = 512 uint4
#pragma unroll
        for (int i = tid; i < 512; i += 256) {
            int row = i >> 3, q = i & 7;
            *(uint4*)(As + row * 80 + q * 8) =
                *(const uint4*)(g_in_h + (size_t)(grow + row) * D_IN + kc + q * 8);
        }
        // B chunk: 64x256 halves = 2048 uint4
#pragma unroll
        for (int i = tid; i < 2048; i += 256) {
            int row = i >> 5, q = i & 31;
            *(uint4*)(Bs + row * 272 + q * 8) =
                *(const uint4*)(g_w_h + (size_t)(kc + row) * D_OUT + q * 8);
        }
        __syncthreads();
#pragma unroll
        for (int kk = 0; kk < 4; kk++) {
            wmma::fragment<wmma::matrix_a, 16, 16, 16, __half, wmma::row_major> af;
            wmma::load_matrix_sync(af, As + m0 * 80 + kk * 16, 80);
#pragma unroll
            for (int nt = 0; nt < 8; nt++) {
                wmma::fragment<wmma::matrix_b, 16, 16, 16, __half, wmma::row_major> bf;
                wmma::load_matrix_sync(bf, Bs + kk * 16 * 272 + n0 + nt * 16, 272);
                wmma::mma_sync(acc[nt], af, bf, acc[nt]);
            }
        }
    }
#pragma unroll
    for (int nt = 0; nt < 8; nt++)
        wmma::store_matrix_sync(g_Wh + (size_t)(grow + m0) * D_OUT + n0 + nt * 16,
                                acc[nt], D_OUT, wmma::mem_row_major);
}

// ---------------- s = Wh@a1, t = Wh@a2 (warp per row) ----------------
__global__ __launch_bounds__(256) void st_kernel(const float* __restrict__ a) {
    int warp = threadIdx.x >> 5, lane = threadIdx.x & 31;
    int row = blockIdx.x * 8 + warp;
    float s = 0.f, t = 0.f;
#pragma unroll
    for (int k = lane; k < 256; k += 32) {
        float w = g_Wh[(size_t)row * D_OUT + k];
        s += w * a[k];
        t += w * a[k + 256];
    }
#pragma unroll
    for (int off = 16; off; off >>= 1) {
        s += __shfl_down_sync(0xffffffffu, s, off);
        t += __shfl_down_sync(0xffffffffu, t, off);
    }
    if (lane == 0) { g_s[row] = s; g_t[row] = t; }
}

// ---------------- B1/B2 = scaled [Wh | 1 | 0] in fp16 ----------------
__global__ __launch_bounds__(288) void buildB_kernel() {
    int j = blockIdx.x, d = threadIdx.x;   // blockDim = 288
    float tj = g_t[j];
    float E1 = expf(tj), E2 = expf(0.2f * tj);
    float v = (d < 256) ? g_Wh[(size_t)j * D_OUT + d] : (d == 256 ? 1.0f : 0.0f);
    g_B1[(size_t)j * PN + d] = __float2half(v * E1);
    g_B2[(size_t)j * PN + d] = __float2half(v * E2);
}

// ---------------- fused attention: two masked 0/1 GEMMs + epilogue ----------------
// smem layout (dynamic):
//   [0      .. 10240)  A1s  64x80 half
//   [10240  .. 20480)  A2s  64x80 half
//   [20480  .. 57344)  B1s  64x288 half
//   [57344  .. 94208)  B2s  64x288 half
//   epilogue overlay: Sh1 fp32 64x288 @0 (73728B), Sh2 @73728 (73728B)
//   [147456 .. 148736) t_sh,s_sh,F1,F2,Zi (5 x 64 floats)
#define SMEM_ATTN 148736

__global__ __launch_bounds__(256, 1) void attn_kernel(const int* __restrict__ adj,
                                                      float* __restrict__ out) {
    extern __shared__ char smem[];
    __half* A1s = (__half*)smem;
    __half* A2s = (__half*)(smem + 10240);
    __half* B1s = (__half*)(smem + 20480);
    __half* B2s = (__half*)(smem + 57344);
    float*  Sh1 = (float*)smem;
    float*  Sh2 = (float*)(smem + 73728);
    float*  t_sh = (float*)(smem + 147456);
    float*  s_sh = t_sh + 64;
    float*  F1_sh = s_sh + 64;
    float*  F2_sh = F1_sh + 64;
    float*  Zi_sh = F2_sh + 64;

    int tid  = threadIdx.x;
    int warp = tid >> 5;
    int grow = blockIdx.x * 64;
    int m0 = (warp >> 1) * 16;       // 4 M-tiles of 16
    int n0 = (warp & 1) * 144;       // 2 N halves, 9 tiles of 16 each

    if (tid < 64) s_sh[tid] = g_s[grow + tid];

    wmma::fragment<wmma::accumulator, 16, 16, 16, float> acc1[9], acc2[9];
#pragma unroll
    for (int i = 0; i < 9; i++) { wmma::fill_fragment(acc1[i], 0.f); wmma::fill_fragment(acc2[i], 0.f); }

    for (int jc = 0; jc < N_NODES; jc += 64) {
        __syncthreads();   // previous chunk's smem reads complete; s_sh visible (1st iter)

        // adjacency chunk into registers (64x64 ints = 1024 int4)
        int4 av[4];
#pragma unroll
        for (int i = 0; i < 4; i++) {
            int u = tid + i * 256;
            int row = u >> 4, c4 = u & 15;
            av[i] = *(const int4*)(adj + (size_t)(grow + row) * N_NODES + jc + c4 * 4);
        }
        if (tid < 64) t_sh[tid] = g_t[jc + tid];

        // stage B1/B2 chunk (contiguous: full rows) 2304 uint4 each
        const uint4* src1 = (const uint4*)(g_B1 + (size_t)jc * PN);
        const uint4* src2 = (const uint4*)(g_B2 + (size_t)jc * PN);
        uint4* d1 = (uint4*)B1s;
        uint4* d2 = (uint4*)B2s;
#pragma unroll
        for (int i = 0; i < 9; i++) d1[tid + i * 256] = src1[tid + i * 256];
#pragma unroll
        for (int i = 0; i < 9; i++) d2[tid + i * 256] = src2[tid + i * 256];

        __syncthreads();   // t_sh / B_sh ready

        // build A1 (adj & pos), A2 (adj & neg) tiles in fp16 (0/1 exact)
#pragma unroll
        for (int i = 0; i < 4; i++) {
            int u = tid + i * 256;
            int row = u >> 4, c4 = u & 15;
            float sr = s_sh[row];
            const int* avp = (const int*)&av[i];
            __half h1[4], h2[4];
#pragma unroll
            for (int k = 0; k < 4; k++) {
                bool msk = avp[k] > 0;
                bool pos = (sr + t_sh[c4 * 4 + k]) > 0.f;
                h1[k] = __float2half((msk && pos)  ? 1.f : 0.f);
                h2[k] = __float2half((msk && !pos) ? 1.f : 0.f);
            }
            *(__half2*)(A1s + row * 80 + c4 * 4)     = __halves2half2(h1[0], h1[1]);
            *(__half2*)(A1s + row * 80 + c4 * 4 + 2) = __halves2half2(h1[2], h1[3]);
            *(__half2*)(A2s + row * 80 + c4 * 4)     = __halves2half2(h2[0], h2[1]);
            *(__half2*)(A2s + row * 80 + c4 * 4 + 2) = __halves2half2(h2[2], h2[3]);
        }
        __syncthreads();   // A tiles ready

        // two masked GEMMs
#pragma unroll
        for (int kk = 0; kk < 4; kk++) {
            wmma::fragment<wmma::matrix_a, 16, 16, 16, __half, wmma::row_major> a1f, a2f;
            wmma::load_matrix_sync(a1f, A1s + m0 * 80 + kk * 16, 80);
            wmma::load_matrix_sync(a2f, A2s + m0 * 80 + kk * 16, 80);
#pragma unroll
            for (int nt = 0; nt < 9; nt++) {
                wmma::fragment<wmma::matrix_b, 16, 16, 16, __half, wmma::row_major> b1f, b2f;
                wmma::load_matrix_sync(b1f, B1s + kk * 16 * PN + n0 + nt * 16, PN);
                wmma::mma_sync(acc1[nt], a1f, b1f, acc1[nt]);
                wmma::load_matrix_sync(b2f, B2s + kk * 16 * PN + n0 + nt * 16, PN);
                wmma::mma_sync(acc2[nt], a2f, b2f, acc2[nt]);
            }
        }
    }

    // ---- epilogue: out = elu( (F1*S1 + F2*S2) / (F1*S1z + F2*S2z) ) ----
    __syncthreads();  // all mma smem reads done before overlaying Sh1/Sh2
#pragma unroll
    for (int nt = 0; nt < 9; nt++) {
        wmma::store_matrix_sync(Sh1 + m0 * PN + n0 + nt * 16, acc1[nt], PN, wmma::mem_row_major);
        wmma::store_matrix_sync(Sh2 + m0 * PN + n0 + nt * 16, acc2[nt], PN, wmma::mem_row_major);
    }
    __syncthreads();
    if (tid < 64) {
        float sv = s_sh[tid];
        float f1 = expf(sv), f2 = expf(0.2f * sv);
        F1_sh[tid] = f1;
        F2_sh[tid] = f2;
        float Z = f1 * Sh1[tid * PN + 256] + f2 * Sh2[tid * PN + 256];
        Zi_sh[tid] = (Z > 0.f) ? (1.f / Z) : 0.f;   // Z==0 impossible for random adj; guard anyway
    }
    __syncthreads();
#pragma unroll 4
    for (int r = 0; r < 64; r++) {
        float val = (F1_sh[r] * Sh1[r * PN + tid] + F2_sh[r] * Sh2[r * PN + tid]) * Zi_sh[r];
        out[(size_t)(grow + r) * D_OUT + tid] = (val > 0.f) ? val : expm1f(val);
    }
}

// ---------------- launch ----------------
extern "C" void kernel_launch(void* const* d_in, const int* in_sizes, int n_in,
                              void* d_out, int out_size) {
    const float* input  = nullptr;
    const int*   adj    = nullptr;
    const float* weight = nullptr;
    const float* a      = nullptr;
    for (int i = 0; i < n_in; i++) {
        switch (in_sizes[i]) {
            case N_NODES * D_IN:    input  = (const float*)d_in[i]; break;
            case 67108864:          adj    = (const int*)d_in[i];   break;  // 8192*8192
            case D_IN * D_OUT:      weight = (const float*)d_in[i]; break;
            case 2 * D_OUT:         a      = (const float*)d_in[i]; break;
        }
    }

    // attn kernel needs >48KB dynamic smem
    cudaFuncSetAttribute(attn_kernel, cudaFuncAttributeMaxDynamicSharedMemorySize, SMEM_ATTN);

    // resolve device-symbol addresses for the converter
    __half* in_h;  cudaGetSymbolAddress((void**)&in_h, g_in_h);
    __half* w_h;   cudaGetSymbolAddress((void**)&w_h,  g_w_h);

    f2h_kernel<<<4096, 256>>>(input,  in_h, N_NODES * D_IN);
    f2h_kernel<<<512,  256>>>(weight, w_h,  D_IN * D_OUT);

    gemm_wh_kernel<<<N_NODES / 64, 256>>>();
    st_kernel<<<N_NODES / 8, 256>>>(a);
    buildB_kernel<<<N_NODES, 288>>>();
    attn_kernel<<<N_NODES / 64, 256, SMEM_ATTN>>>(adj, (float*)d_out);
}

// round 5
// speedup vs baseline: 3.3212x; 3.3212x over previous
#include <cuda_runtime.h>
#include <cuda_fp16.h>
#include <mma.h>

using namespace nvcuda;

#define N_NODES 8192
#define D_IN    512
#define D_OUT   256
#define NCHUNK  128            // N_NODES / 64

// ---------------- scratch (static device arrays; no allocation) ----------------
__device__ __align__(16) __half g_in_h[N_NODES * D_IN];
__device__ __align__(16) __half g_w_h[D_IN * D_OUT];
__device__ __align__(16) float  g_Wh[N_NODES * D_OUT];
__device__ float  g_s[N_NODES];
__device__ float  g_t[N_NODES];
__device__ __align__(16) __half  g_Bh[N_NODES * D_OUT];   // fp16 Wh
__device__ __align__(16) float2  g_Qq[N_NODES];            // (e^{t_j}, e^{0.2 t_j})

// ---------------- cp.async helpers ----------------
__device__ __forceinline__ void cpa16(void* dst, const void* src) {
    unsigned d = (unsigned)__cvta_generic_to_shared(dst);
    asm volatile("cp.async.cg.shared.global [%0], [%1], 16;\n" :: "r"(d), "l"(src));
}
#define CP_COMMIT() asm volatile("cp.async.commit_group;\n")
#define CP_WAIT0()  asm volatile("cp.async.wait_group 0;\n" ::: "memory")

// ---------------- fp32 -> fp16 convert ----------------
__global__ void f2h_kernel(const float* __restrict__ x, __half* __restrict__ y, int n) {
    int i = blockIdx.x * blockDim.x + threadIdx.x;
    int stride = gridDim.x * blockDim.x;
    for (; i < n; i += stride) y[i] = __float2half(x[i]);
}

// ---------------- Wh = input @ weight (wmma fp16, fp32 accum) ----------------
__global__ __launch_bounds__(256) void gemm_wh_kernel() {
    __shared__ __half As[64 * 80];
    __shared__ __half Bs[64 * 272];
    int tid  = threadIdx.x;
    int warp = tid >> 5;
    int grow = blockIdx.x * 64;
    int m0 = (warp >> 1) * 16;
    int n0 = (warp & 1) * 128;

    wmma::fragment<wmma::accumulator, 16, 16, 16, float> acc[8];
#pragma unroll
    for (int i = 0; i < 8; i++) wmma::fill_fragment(acc[i], 0.0f);

    for (int kc = 0; kc < D_IN; kc += 64) {
        __syncthreads();
#pragma unroll
        for (int i = tid; i < 512; i += 256) {
            int row = i >> 3, q = i & 7;
            *(uint4*)(As + row * 80 + q * 8) =
                *(const uint4*)(g_in_h + (size_t)(grow + row) * D_IN + kc + q * 8);
        }
#pragma unroll
        for (int i = tid; i < 2048; i += 256) {
            int row = i >> 5, q = i & 31;
            *(uint4*)(Bs + row * 272 + q * 8) =
                *(const uint4*)(g_w_h + (size_t)(kc + row) * D_OUT + q * 8);
        }
        __syncthreads();
#pragma unroll
        for (int kk = 0; kk < 4; kk++) {
            wmma::fragment<wmma::matrix_a, 16, 16, 16, __half, wmma::row_major> af;
            wmma::load_matrix_sync(af, As + m0 * 80 + kk * 16, 80);
#pragma unroll
            for (int nt = 0; nt < 8; nt++) {
                wmma::fragment<wmma::matrix_b, 16, 16, 16, __half, wmma::row_major> bf;
                wmma::load_matrix_sync(bf, Bs + kk * 16 * 272 + n0 + nt * 16, 272);
                wmma::mma_sync(acc[nt], af, bf, acc[nt]);
            }
        }
    }
#pragma unroll
    for (int nt = 0; nt < 8; nt++)
        wmma::store_matrix_sync(g_Wh + (size_t)(grow + m0) * D_OUT + n0 + nt * 16,
                                acc[nt], D_OUT, wmma::mem_row_major);
}

// ---------------- s = Wh@a1, t = Wh@a2 ----------------
__global__ __launch_bounds__(256) void st_kernel(const float* __restrict__ a) {
    int warp = threadIdx.x >> 5, lane = threadIdx.x & 31;
    int row = blockIdx.x * 8 + warp;
    float s = 0.f, t = 0.f;
#pragma unroll
    for (int k = lane; k < 256; k += 32) {
        float w = g_Wh[(size_t)row * D_OUT + k];
        s += w * a[k];
        t += w * a[k + 256];
    }
#pragma unroll
    for (int off = 16; off; off >>= 1) {
        s += __shfl_down_sync(0xffffffffu, s, off);
        t += __shfl_down_sync(0xffffffffu, t, off);
    }
    if (lane == 0) { g_s[row] = s; g_t[row] = t; }
}

// ---------------- Bh = fp16(Wh); Qq = (e^t, e^{0.2t}) ----------------
__global__ __launch_bounds__(256) void buildB_kernel() {
    int j = blockIdx.x, d = threadIdx.x;
    g_Bh[(size_t)j * D_OUT + d] = __float2half(g_Wh[(size_t)j * D_OUT + d]);
    if (d == 0) {
        float tj = g_t[j];
        g_Qq[j] = make_float2(expf(tj), expf(0.2f * tj));
    }
}

// ---------------- fused attention: ONE masked GEMM + epilogue ----------------
// smem layout (bytes):
//   [0     .. 18432)   A bufs: 2 x (64 x 72 half)  = 2 x 9216
//   [18432 .. 86016)   B bufs: 2 x (64 x 264 half) = 2 x 33792
//   [86016 .. 87040)   Qq:     2 x 64 float2
//   [87040 .. 87296)   Zinv:   64 float
//   epilogue overlay:  Sh fp32 64 x 260 @0 (66560 B)
#define OFF_B   18432
#define OFF_QQ  86016
#define OFF_Z   87040
#define SMEM_ATTN 87296
#define A_BUF_H 4608    // halves per A buffer (64*72)
#define B_BUF_H 16896   // halves per B buffer (64*264)

__device__ __forceinline__ void load_adj4(int4* dst, const int* __restrict__ adj,
                                          int grow, int row, int c, int cg) {
    const int4* p = (const int4*)(adj + (size_t)(grow + row) * N_NODES + c * 64 + cg * 16);
    dst[0] = p[0]; dst[1] = p[1]; dst[2] = p[2]; dst[3] = p[3];
}

// build 16 fp16 attention weights for (row, cols cg*16..+16); returns partial Z
__device__ __forceinline__ float build_strip(__half* Adst, const float2* __restrict__ qsrc,
                                             const int4* aregs, float P, float p,
                                             int row, int cg) {
    const int* ap = (const int*)aregs;
    __align__(16) __half h[16];
    float z = 0.f;
#pragma unroll
    for (int k = 0; k < 16; k++) {
        float2 qq = qsrc[k];
        float v1 = P * qq.x;                 // e^{s_i + t_j}
        float v  = (v1 > 1.0f) ? v1 : p * qq.y;   // LeakyReLU branch via e^{s+t} > 1
        v = (ap[k] != 0) ? v : 0.0f;         // adjacency mask
        z += v;
        h[k] = __float2half(v);
    }
    uint4* dp = (uint4*)(Adst + row * 72 + cg * 16);
    dp[0] = *(const uint4*)&h[0];
    dp[1] = *(const uint4*)&h[8];
    return z;
}

__global__ __launch_bounds__(256, 1) void attn_kernel(const int* __restrict__ adj,
                                                      float* __restrict__ out) {
    extern __shared__ char smem[];
    __half* Asm = (__half*)smem;
    __half* Bsm = (__half*)(smem + OFF_B);
    float2* Qsm = (float2*)(smem + OFF_QQ);
    float*  Zs  = (float*)(smem + OFF_Z);

    int tid  = threadIdx.x;
    int warp = tid >> 5;
    int grow = blockIdx.x * 64;
    int row  = tid >> 2;          // A-build: one row per 4 threads
    int cg   = tid & 3;           // 16-col group within row
    int m0 = (warp & 1) * 32;     // 2 m-splits x 16x2 tiles
    int n0 = (warp >> 1) * 64;    // 4 n-splits x 16x4 tiles

    float s = g_s[grow + row];
    float P = expf(s), p = expf(0.2f * s);

    // --- issue group(0): B(0)->buf0, Qq(0)->slot0, Qq(1)->slot1 ---
    {
        const char* bsrc = (const char*)g_Bh;
        char* bdst = (char*)Bsm;
#pragma unroll
        for (int i = 0; i < 8; i++) {
            int idx = tid + i * 256;
            int r = idx >> 5, sg = idx & 31;
            cpa16(bdst + r * 528 + sg * 16, bsrc + r * 512 + sg * 16);
        }
        if (tid < 32) {
            cpa16((char*)Qsm + tid * 16, (const char*)g_Qq + tid * 16);
            cpa16((char*)Qsm + 512 + tid * 16, (const char*)g_Qq + 512 + tid * 16);
        }
        CP_COMMIT();
    }

    int4 a_cur[4], a_next[4];
    load_adj4(a_cur, adj, grow, row, 0, cg);

    wmma::fragment<wmma::accumulator, 16, 16, 16, float> acc[2][4];
#pragma unroll
    for (int mi = 0; mi < 2; mi++)
#pragma unroll
        for (int ni = 0; ni < 4; ni++) wmma::fill_fragment(acc[mi][ni], 0.f);

    float zacc = 0.f;

    CP_WAIT0();
    __syncthreads();
    zacc += build_strip(Asm, Qsm + cg * 16, a_cur, P, p, row, cg);   // A(0)
    load_adj4(a_cur, adj, grow, row, 1, cg);
    __syncthreads();
    // --- issue group(1): B(1)->buf1, Qq(2)->slot0 ---
    {
        const char* bsrc = (const char*)g_Bh + (size_t)1 * 64 * 512;
        char* bdst = (char*)Bsm + B_BUF_H * 2;
#pragma unroll
        for (int i = 0; i < 8; i++) {
            int idx = tid + i * 256;
            int r = idx >> 5, sg = idx & 31;
            cpa16(bdst + r * 528 + sg * 16, bsrc + r * 512 + sg * 16);
        }
        if (tid < 32)
            cpa16((char*)Qsm + tid * 16, (const char*)g_Qq + 2 * 512 + tid * 16);
        CP_COMMIT();
    }

    for (int jc = 0; jc < NCHUNK; jc++) {
        int buf = jc & 1, nbuf = buf ^ 1;

        if (jc + 2 < NCHUNK) load_adj4(a_next, adj, grow, row, jc + 2, cg);

        // build A(jc+1) while tensor pipe works on MMA(jc)
        if (jc + 1 < NCHUNK)
            zacc += build_strip(Asm + nbuf * A_BUF_H, Qsm + nbuf * 64 + cg * 16,
                                a_cur, P, p, row, cg);

        // MMA(jc): C += A(jc) @ B(jc)
        {
            const __half* Ab = Asm + buf * A_BUF_H;
            const __half* Bb = Bsm + buf * B_BUF_H;
#pragma unroll
            for (int kk = 0; kk < 4; kk++) {
                wmma::fragment<wmma::matrix_a, 16, 16, 16, __half, wmma::row_major> af0, af1;
                wmma::load_matrix_sync(af0, Ab + (m0)      * 72 + kk * 16, 72);
                wmma::load_matrix_sync(af1, Ab + (m0 + 16) * 72 + kk * 16, 72);
#pragma unroll
                for (int ni = 0; ni < 4; ni++) {
                    wmma::fragment<wmma::matrix_b, 16, 16, 16, __half, wmma::row_major> bf;
                    wmma::load_matrix_sync(bf, Bb + kk * 16 * 264 + n0 + ni * 16, 264);
                    wmma::mma_sync(acc[0][ni], af0, bf, acc[0][ni]);
                    wmma::mma_sync(acc[1][ni], af1, bf, acc[1][ni]);
                }
            }
        }

        CP_WAIT0();
        __syncthreads();

        // issue group(jc+2): B(jc+2)->buf, Qq(jc+3 clamped)->nbuf
        if (jc + 2 < NCHUNK) {
            int qc = (jc + 3 < NCHUNK) ? (jc + 3) : (NCHUNK - 1);
            const char* bsrc = (const char*)g_Bh + (size_t)(jc + 2) * 64 * 512;
            char* bdst = (char*)Bsm + buf * (B_BUF_H * 2);
#pragma unroll
            for (int i = 0; i < 8; i++) {
                int idx = tid + i * 256;
                int r = idx >> 5, sg = idx & 31;
                cpa16(bdst + r * 528 + sg * 16, bsrc + r * 512 + sg * 16);
            }
            if (tid < 32)
                cpa16((char*)Qsm + nbuf * 512 + tid * 16,
                      (const char*)g_Qq + (size_t)qc * 512 + tid * 16);
            CP_COMMIT();
        }

#pragma unroll
        for (int q = 0; q < 4; q++) a_cur[q] = a_next[q];
    }

    // ---- epilogue: out = elu( numerator / Z ) ----
    __syncthreads();           // all MMA smem reads done; no cp.async pending
    float* Sh = (float*)smem;  // 64 x 260 fp32 overlay
#pragma unroll
    for (int mi = 0; mi < 2; mi++)
#pragma unroll
        for (int ni = 0; ni < 4; ni++)
            wmma::store_matrix_sync(Sh + (m0 + mi * 16) * 260 + n0 + ni * 16,
                                    acc[mi][ni], 260, wmma::mem_row_major);

    // Z: reduce zacc across the 4 col-group lanes of each row
    float z = zacc;
    z += __shfl_down_sync(0xffffffffu, z, 1);
    z += __shfl_down_sync(0xffffffffu, z, 2);
    if (cg == 0) Zs[row] = (z > 0.f) ? (1.0f / z) : 0.f;
    __syncthreads();

#pragma unroll 4
    for (int r = 0; r < 64; r++) {
        float val = Sh[r * 260 + tid] * Zs[r];
        out[(size_t)(grow + r) * D_OUT + tid] = (val > 0.f) ? val : expm1f(val);
    }
}

// ---------------- launch ----------------
extern "C" void kernel_launch(void* const* d_in, const int* in_sizes, int n_in,
                              void* d_out, int out_size) {
    const float* input  = nullptr;
    const int*   adj    = nullptr;
    const float* weight = nullptr;
    const float* a      = nullptr;
    for (int i = 0; i < n_in; i++) {
        switch (in_sizes[i]) {
            case N_NODES * D_IN:    input  = (const float*)d_in[i]; break;
            case 67108864:          adj    = (const int*)d_in[i];   break;
            case D_IN * D_OUT:      weight = (const float*)d_in[i]; break;
            case 2 * D_OUT:         a      = (const float*)d_in[i]; break;
        }
    }

    cudaFuncSetAttribute(attn_kernel, cudaFuncAttributeMaxDynamicSharedMemorySize, SMEM_ATTN);

    __half* in_h;  cudaGetSymbolAddress((void**)&in_h, g_in_h);
    __half* w_h;   cudaGetSymbolAddress((void**)&w_h,  g_w_h);

    f2h_kernel<<<4096, 256>>>(input,  in_h, N_NODES * D_IN);
    f2h_kernel<<<512,  256>>>(weight, w_h,  D_IN * D_OUT);

    gemm_wh_kernel<<<N_NODES / 64, 256>>>();
    st_kernel<<<N_NODES / 8, 256>>>(a);
    buildB_kernel<<<N_NODES, 256>>>();
    attn_kernel<<<N_NODES / 64, 256, SMEM_ATTN>>>(adj, (float*)d_out);
}

// round 7
// speedup vs baseline: 3.9524x; 1.1901x over previous
#include <cuda_runtime.h>
#include <cuda_fp16.h>
#include <mma.h>
#include <cstdint>

using namespace nvcuda;

#define N_NODES 8192
#define D_IN    512
#define D_OUT   256
#define NCHUNK  128
#define M_CTA   64

// smem layout (bytes)
#define A_BUF   9216            // 64 x 72 halves
#define OFF_B   18432           // 2 A bufs
#define B_BUF   33792           // 64 x 264 halves
#define OFF_Q   119808          // after 3 B bufs
#define OFF_Z   121856          // after 4x512B Q ring
#define SMEM_ATTN 122112

// ---------------- scratch (static device arrays; no allocation) ----------------
__device__ __align__(16) __half  g_w_h[D_IN * D_OUT];
__device__ __align__(16) float   g_Wh[(size_t)N_NODES * D_OUT];
__device__ float                 g_s[N_NODES];
__device__ __align__(16) float2  g_Qq[N_NODES];                 // (e^{t_j}, e^{0.2 t_j})
__device__ __align__(16) __half  g_Bh[(size_t)N_NODES * D_OUT]; // fp16 Wh

// ---------------- helpers ----------------
__device__ __forceinline__ void cpa16(void* dst, const void* src) {
    unsigned d = (unsigned)__cvta_generic_to_shared(dst);
    asm volatile("cp.async.cg.shared.global [%0], [%1], 16;\n" :: "r"(d), "l"(src));
}
#define CP_COMMIT() asm volatile("cp.async.commit_group;\n")

__device__ __forceinline__ void bar_sync(int id, int cnt) {
    asm volatile("bar.sync %0, %1;" :: "r"(id), "r"(cnt) : "memory");
}
__device__ __forceinline__ void bar_arrive(int id, int cnt) {
    asm volatile("bar.arrive %0, %1;" :: "r"(id), "r"(cnt) : "memory");
}

// ---------------- fp32 -> fp16 convert (weight) ----------------
__global__ void f2h_kernel(const float* __restrict__ x, __half* __restrict__ y, int n) {
    int i = blockIdx.x * blockDim.x + threadIdx.x;
    int stride = gridDim.x * blockDim.x;
    for (; i < n; i += stride) y[i] = __float2half(x[i]);
}

// ---------------- Wh = input @ weight (wmma, fp32 accum) ----------------
__global__ __launch_bounds__(256) void gemm_wh_kernel(const float* __restrict__ input) {
    __shared__ __half As[64 * 80];
    __shared__ __half Bs[64 * 272];
    int tid  = threadIdx.x;
    int warp = tid >> 5;
    int grow = blockIdx.x * 64;
    int m0 = (warp >> 1) * 16;
    int n0 = (warp & 1) * 128;

    wmma::fragment<wmma::accumulator, 16, 16, 16, float> acc[8];
#pragma unroll
    for (int i = 0; i < 8; i++) wmma::fill_fragment(acc[i], 0.0f);

    for (int kc = 0; kc < D_IN; kc += 64) {
        __syncthreads();
#pragma unroll
        for (int i = tid; i < 1024; i += 256) {
            int row = i >> 4, q = i & 15;
            float4 f = *(const float4*)(input + (size_t)(grow + row) * D_IN + kc + q * 4);
            *(__half2*)(As + row * 80 + q * 4)     = __floats2half2_rn(f.x, f.y);
            *(__half2*)(As + row * 80 + q * 4 + 2) = __floats2half2_rn(f.z, f.w);
        }
#pragma unroll
        for (int i = tid; i < 2048; i += 256) {
            int row = i >> 5, q = i & 31;
            *(uint4*)(Bs + row * 272 + q * 8) =
                *(const uint4*)(g_w_h + (size_t)(kc + row) * D_OUT + q * 8);
        }
        __syncthreads();
#pragma unroll
        for (int kk = 0; kk < 4; kk++) {
            wmma::fragment<wmma::matrix_a, 16, 16, 16, __half, wmma::row_major> af;
            wmma::load_matrix_sync(af, As + m0 * 80 + kk * 16, 80);
#pragma unroll
            for (int nt = 0; nt < 8; nt++) {
                wmma::fragment<wmma::matrix_b, 16, 16, 16, __half, wmma::row_major> bf;
                wmma::load_matrix_sync(bf, Bs + kk * 16 * 272 + n0 + nt * 16, 272);
                wmma::mma_sync(acc[nt], af, bf, acc[nt]);
            }
        }
    }
#pragma unroll
    for (int nt = 0; nt < 8; nt++)
        wmma::store_matrix_sync(g_Wh + (size_t)(grow + m0) * D_OUT + n0 + nt * 16,
                                acc[nt], D_OUT, wmma::mem_row_major);
}

// ---------------- s = Wh@a1; Qq = (e^t, e^{0.2t}) ----------------
__global__ __launch_bounds__(256) void st_kernel(const float* __restrict__ a) {
    int warp = threadIdx.x >> 5, lane = threadIdx.x & 31;
    int row = blockIdx.x * 8 + warp;
    float s = 0.f, t = 0.f;
#pragma unroll
    for (int k = lane; k < 256; k += 32) {
        float w = g_Wh[(size_t)row * D_OUT + k];
        s += w * a[k];
        t += w * a[k + 256];
    }
#pragma unroll
    for (int off = 16; off; off >>= 1) {
        s += __shfl_down_sync(0xffffffffu, s, off);
        t += __shfl_down_sync(0xffffffffu, t, off);
    }
    if (lane == 0) {
        g_s[row] = s;
        g_Qq[row] = make_float2(expf(t), expf(0.2f * t));
    }
}

// ---------------- g_Bh = fp16(g_Wh) ----------------
__global__ __launch_bounds__(256) void h_convert_kernel() {
    size_t i = (size_t)(blockIdx.x * blockDim.x + threadIdx.x) * 8;
    float4 a = *(const float4*)(g_Wh + i);
    float4 b = *(const float4*)(g_Wh + i + 4);
    __align__(16) __half2 h[4];
    h[0] = __floats2half2_rn(a.x, a.y);
    h[1] = __floats2half2_rn(a.z, a.w);
    h[2] = __floats2half2_rn(b.x, b.y);
    h[3] = __floats2half2_rn(b.z, b.w);
    *(uint4*)(g_Bh + i) = *(const uint4*)h;
}

// ---------------- attention: warp-specialized producer/consumer ----------------

// build 32 fp16 attention weights for (row, cols half*32..+32); returns partial Z
__device__ __forceinline__ float build32(__half* Ab, const float2* qb, const int4* av,
                                         float P, float p, int row, int half) {
    float z = 0.f;
    __align__(16) __half h[32];
#pragma unroll
    for (int q = 0; q < 8; q++) {
        int4 a = av[q];
        float2 q0 = qb[q * 4 + 0], q1 = qb[q * 4 + 1];
        float2 q2 = qb[q * 4 + 2], q3 = qb[q * 4 + 3];
        // exp(leaky(s+t)) = max(e^s e^t, e^{0.2s} e^{0.2t})
        float v0 = fmaxf(P * q0.x, p * q0.y); v0 = a.x ? v0 : 0.f;
        float v1 = fmaxf(P * q1.x, p * q1.y); v1 = a.y ? v1 : 0.f;
        float v2 = fmaxf(P * q2.x, p * q2.y); v2 = a.z ? v2 : 0.f;
        float v3 = fmaxf(P * q3.x, p * q3.y); v3 = a.w ? v3 : 0.f;
        z += (v0 + v1) + (v2 + v3);
        h[q * 4 + 0] = __float2half(v0);
        h[q * 4 + 1] = __float2half(v1);
        h[q * 4 + 2] = __float2half(v2);
        h[q * 4 + 3] = __float2half(v3);
    }
    uint4* d = (uint4*)(Ab + row * 72 + half * 32);
    d[0] = *(const uint4*)&h[0];
    d[1] = *(const uint4*)&h[8];
    d[2] = *(const uint4*)&h[16];
    d[3] = *(const uint4*)&h[24];
    return z;
}

__device__ __forceinline__ void prod_iter(int c, char* smem, const int* aptr,
                                          const int4* bld, int4* pre,
                                          int ptid, int prow, int phalf,
                                          float P, float p, float& zacc,
                                          float* Zs, const float2* Qbase) {
    if (c >= 2) bar_sync(3 + (c & 1), 384);                 // consumers done chunk c-2
    if (c + 1 < NCHUNK) {
        const char* bs = (const char*)g_Bh + (size_t)(c + 1) * 32768;
        char* bd = smem + OFF_B + ((c + 1) % 3) * B_BUF;
#pragma unroll
        for (int i = 0; i < 16; i++) {
            int idx = ptid + i * 128;
            int r = idx >> 5, sg = idx & 31;
            cpa16(bd + r * 528 + sg * 16, bs + (size_t)r * 512 + sg * 16);
        }
        if (ptid < 32 && c + 2 < NCHUNK)
            cpa16((char*)Qbase + ((c + 2) & 3) * 512 + ptid * 16,
                  (const char*)g_Qq + (size_t)(c + 2) * 512 + ptid * 16);
        CP_COMMIT();
#pragma unroll
        for (int q = 0; q < 8; q++)
            pre[q] = ((const int4*)(aptr + (c + 1) * 64))[q];   // prefetch adj(c+1)
    }
    zacc += build32((__half*)(smem + (c & 1) * A_BUF),
                    Qbase + (c & 3) * 64 + phalf * 32, bld, P, p, prow, phalf);
    if (c == NCHUNK - 1) {
        float z = zacc;
        z += __shfl_xor_sync(0xffffffffu, z, 1);
        if (phalf == 0) Zs[prow] = (z > 0.f) ? 1.f / z : 0.f;
    }
    if (c + 1 < NCHUNK) { asm volatile("cp.async.wait_group 1;" ::: "memory"); }
    else                { asm volatile("cp.async.wait_group 0;" ::: "memory"); }
    asm volatile("membar.cta;" ::: "memory");
    bar_arrive(1 + (c & 1), 384);                           // chunk c FULL
}

__global__ __launch_bounds__(384, 1) void attn_kernel(const int* __restrict__ adj,
                                                      float* __restrict__ out) {
    extern __shared__ __align__(16) char smem[];
    int tid  = threadIdx.x;
    int warp = tid >> 5;
    int grow = blockIdx.x * M_CTA;

    if (warp >= 8) {
        // ======================= PRODUCERS (warps 8-11) =======================
        int ptid  = tid - 256;          // 0..127
        int prow  = ptid >> 1;          // 0..63
        int phalf = ptid & 1;           // 32-col half
        float2* Qbase = (float2*)(smem + OFF_Q);
        float*  Zs    = (float*)(smem + OFF_Z);

        // G0: B(0)->buf0, Q(0),Q(1)
        {
            const char* bs = (const char*)g_Bh;
            char* bd = smem + OFF_B;
#pragma unroll
            for (int i = 0; i < 16; i++) {
                int idx = ptid + i * 128;
                int r = idx >> 5, sg = idx & 31;
                cpa16(bd + r * 528 + sg * 16, bs + (size_t)r * 512 + sg * 16);
            }
            if (ptid < 32) {
                cpa16((char*)Qbase + ptid * 16,       (const char*)g_Qq + ptid * 16);
                cpa16((char*)Qbase + 512 + ptid * 16, (const char*)g_Qq + 512 + ptid * 16);
            }
            CP_COMMIT();
        }
        // G1: B(1)->buf1, Q(2)
        {
            const char* bs = (const char*)g_Bh + 32768;
            char* bd = smem + OFF_B + B_BUF;
#pragma unroll
            for (int i = 0; i < 16; i++) {
                int idx = ptid + i * 128;
                int r = idx >> 5, sg = idx & 31;
                cpa16(bd + r * 528 + sg * 16, bs + (size_t)r * 512 + sg * 16);
            }
            if (ptid < 32)
                cpa16((char*)Qbase + 1024 + ptid * 16, (const char*)g_Qq + 1024 + ptid * 16);
            CP_COMMIT();
        }

        const int* aptr = adj + (size_t)(grow + prow) * N_NODES + phalf * 32;
        int4 av[8], av2[8];
#pragma unroll
        for (int q = 0; q < 8; q++) av[q] = ((const int4*)aptr)[q];          // adj(0)

        float s = g_s[grow + prow];
        float P = expf(s), p = expf(0.2f * s);
        float zacc = 0.f;

        asm volatile("cp.async.wait_group 1;" ::: "memory");   // G0 done
        bar_sync(6, 128);                                       // Q(0)/Q(1) visible to all producers
        zacc += build32((__half*)smem, Qbase + phalf * 32, av, P, p, prow, phalf);  // A(0)
#pragma unroll
        for (int q = 0; q < 8; q++) av2[q] = ((const int4*)(aptr + 64))[q];  // adj(1)
        asm volatile("membar.cta;" ::: "memory");
        bar_arrive(1, 384);                                     // chunk 0 FULL

        for (int c = 1; c < NCHUNK; c += 2) {
            prod_iter(c,     smem, aptr, av2, av,  ptid, prow, phalf, P, p, zacc, Zs, Qbase);
            if (c + 1 < NCHUNK)
                prod_iter(c + 1, smem, aptr, av,  av2, ptid, prow, phalf, P, p, zacc, Zs, Qbase);
        }
        // done; exit (dangling EMPTY arrivals are harmless)
    } else {
        // ======================= CONSUMERS (warps 0-7) =======================
        int m0 = (warp & 1) * 32;
        int n0 = (warp >> 1) * 64;

        wmma::fragment<wmma::accumulator, 16, 16, 16, float> acc[2][4];
#pragma unroll
        for (int mi = 0; mi < 2; mi++)
#pragma unroll
            for (int ni = 0; ni < 4; ni++) wmma::fill_fragment(acc[mi][ni], 0.f);

        for (int c = 0; c < NCHUNK; c++) {
            bar_sync(1 + (c & 1), 384);                        // wait FULL(c)
            const __half* Ab = (const __half*)(smem + (c & 1) * A_BUF);
            const __half* Bb = (const __half*)(smem + OFF_B + (c % 3) * B_BUF);
#pragma unroll
            for (int kk = 0; kk < 4; kk++) {
                wmma::fragment<wmma::matrix_a, 16, 16, 16, __half, wmma::row_major> af0, af1;
                wmma::load_matrix_sync(af0, Ab + (m0)      * 72 + kk * 16, 72);
                wmma::load_matrix_sync(af1, Ab + (m0 + 16) * 72 + kk * 16, 72);
#pragma unroll
                for (int ni = 0; ni < 4; ni++) {
                    wmma::fragment<wmma::matrix_b, 16, 16, 16, __half, wmma::row_major> bf;
                    wmma::load_matrix_sync(bf, Bb + kk * 16 * 264 + n0 + ni * 16, 264);
                    wmma::mma_sync(acc[0][ni], af0, bf, acc[0][ni]);
                    wmma::mma_sync(acc[1][ni], af1, bf, acc[1][ni]);
                }
            }
            bar_arrive(3 + (c & 1), 384);                      // EMPTY(c)
        }

        // ---- epilogue: out = elu( numerator / Z ) ----
        bar_sync(5, 256);                                      // consumers drained
        float* Sh = (float*)smem;                              // 64 x 260 fp32 overlay
#pragma unroll
        for (int mi = 0; mi < 2; mi++)
#pragma unroll
            for (int ni = 0; ni < 4; ni++)
                wmma::store_matrix_sync(Sh + (m0 + mi * 16) * 260 + n0 + ni * 16,
                                        acc[mi][ni], 260, wmma::mem_row_major);
        bar_sync(5, 256);
        float* Zsf = (float*)(smem + OFF_Z);
#pragma unroll 4
        for (int r = 0; r < 64; r++) {
            float val = Sh[r * 260 + tid] * Zsf[r];
            out[(size_t)(grow + r) * D_OUT + tid] = (val > 0.f) ? val : expm1f(val);
        }
    }
}

// ---------------- launch ----------------
extern "C" void kernel_launch(void* const* d_in, const int* in_sizes, int n_in,
                              void* d_out, int out_size) {
    const float* input  = nullptr;
    const int*   adj    = nullptr;
    const float* weight = nullptr;
    const float* a      = nullptr;
    for (int i = 0; i < n_in; i++) {
        switch (in_sizes[i]) {
            case N_NODES * D_IN:    input  = (const float*)d_in[i]; break;
            case 67108864:          adj    = (const int*)d_in[i];   break;
            case D_IN * D_OUT:      weight = (const float*)d_in[i]; break;
            case 2 * D_OUT:         a      = (const float*)d_in[i]; break;
        }
    }

    cudaFuncSetAttribute(attn_kernel, cudaFuncAttributeMaxDynamicSharedMemorySize, SMEM_ATTN);

    __half* w_h;  cudaGetSymbolAddress((void**)&w_h, g_w_h);

    f2h_kernel<<<512, 256>>>(weight, w_h, D_IN * D_OUT);
    gemm_wh_kernel<<<N_NODES / 64, 256>>>(input);
    st_kernel<<<N_NODES / 8, 256>>>(a);
    h_convert_kernel<<<1024, 256>>>();
    attn_kernel<<<N_NODES / M_CTA, 384, SMEM_ATTN>>>(adj, (float*)d_out);
}

// round 8
// speedup vs baseline: 4.1217x; 1.0428x over previous
#include <cuda_runtime.h>
#include <cuda_fp16.h>
#include <mma.h>
#include <cstdint>

using namespace nvcuda;

#define N_NODES 8192
#define D_IN    512
#define D_OUT   256
#define NCHUNK  128
#define M_CTA   64

// attn smem layout (bytes)
#define A_BUF   9216            // 64 x 72 halves
#define OFF_B   27648           // 3 A bufs
#define B_BUF   33792           // 64 x 264 halves
#define OFF_Q   129024          // 3 B bufs end
#define OFF_Z   131072          // 4 x 512B Q ring
#define SMEM_ATTN 131328

// ---------------- scratch (static device arrays; no allocation) ----------------
__device__ __align__(16) __half  g_w_h[D_IN * D_OUT];
__device__ float                 g_s[N_NODES];
__device__ __align__(16) float2  g_Qq[N_NODES];                 // (e^{t_j}, e^{0.2 t_j})
__device__ __align__(16) __half  g_Bh[(size_t)N_NODES * D_OUT]; // fp16 Wh

// ---------------- helpers ----------------
__device__ __forceinline__ void cpa16(void* dst, const void* src) {
    unsigned d = (unsigned)__cvta_generic_to_shared(dst);
    asm volatile("cp.async.cg.shared.global [%0], [%1], 16;\n" :: "r"(d), "l"(src));
}
#define CP_COMMIT() asm volatile("cp.async.commit_group;\n")

__device__ __forceinline__ void bar_sync(int id, int cnt) {
    asm volatile("bar.sync %0, %1;" :: "r"(id), "r"(cnt) : "memory");
}

// ---------------- fp32 -> fp16 convert (weight) ----------------
__global__ void f2h_kernel(const float* __restrict__ x, __half* __restrict__ y, int n) {
    int i = blockIdx.x * blockDim.x + threadIdx.x;
    int stride = gridDim.x * blockDim.x;
    for (; i < n; i += stride) y[i] = __float2half(x[i]);
}

// ---------------- Wh GEMM + fused epilogue (Bh fp16, s, Qq) ----------------
// dynamic smem: stage As 64x80 + Bs 64x272 (45KB); epilogue overlay Sh 64x260 fp32 (66.6KB)
#define SMEM_GEMM 66560
__global__ __launch_bounds__(256) void gemm_wh_kernel(const float* __restrict__ input,
                                                      const float* __restrict__ a) {
    extern __shared__ __align__(16) char gsm[];
    __half* As = (__half*)gsm;                 // 64 x 80
    __half* Bs = (__half*)(gsm + 10240);       // 64 x 272
    float*  Sh = (float*)gsm;                  // epilogue overlay 64 x 260
    int tid  = threadIdx.x;
    int warp = tid >> 5, lane = tid & 31;
    int grow = blockIdx.x * 64;
    int m0 = (warp >> 1) * 16;
    int n0 = (warp & 1) * 128;

    wmma::fragment<wmma::accumulator, 16, 16, 16, float> acc[8];
#pragma unroll
    for (int i = 0; i < 8; i++) wmma::fill_fragment(acc[i], 0.0f);

    for (int kc = 0; kc < D_IN; kc += 64) {
        __syncthreads();
#pragma unroll
        for (int i = tid; i < 1024; i += 256) {
            int row = i >> 4, q = i & 15;
            float4 f = *(const float4*)(input + (size_t)(grow + row) * D_IN + kc + q * 4);
            *(__half2*)(As + row * 80 + q * 4)     = __floats2half2_rn(f.x, f.y);
            *(__half2*)(As + row * 80 + q * 4 + 2) = __floats2half2_rn(f.z, f.w);
        }
#pragma unroll
        for (int i = tid; i < 2048; i += 256) {
            int row = i >> 5, q = i & 31;
            *(uint4*)(Bs + row * 272 + q * 8) =
                *(const uint4*)(g_w_h + (size_t)(kc + row) * D_OUT + q * 8);
        }
        __syncthreads();
#pragma unroll
        for (int kk = 0; kk < 4; kk++) {
            wmma::fragment<wmma::matrix_a, 16, 16, 16, __half, wmma::row_major> af;
            wmma::load_matrix_sync(af, As + m0 * 80 + kk * 16, 80);
#pragma unroll
            for (int nt = 0; nt < 8; nt++) {
                wmma::fragment<wmma::matrix_b, 16, 16, 16, __half, wmma::row_major> bf;
                wmma::load_matrix_sync(bf, Bs + kk * 16 * 272 + n0 + nt * 16, 272);
                wmma::mma_sync(acc[nt], af, bf, acc[nt]);
            }
        }
    }

    // ---- fused epilogue ----
    __syncthreads();
#pragma unroll
    for (int nt = 0; nt < 8; nt++)
        wmma::store_matrix_sync(Sh + m0 * 260 + n0 + nt * 16, acc[nt], 260, wmma::mem_row_major);
    __syncthreads();

    // fp16 Bh (coalesced per row)
#pragma unroll 4
    for (int r = 0; r < 64; r++)
        g_Bh[(size_t)(grow + r) * D_OUT + tid] = __float2half(Sh[r * 260 + tid]);

    // s, t per row -> g_s, g_Qq
#pragma unroll
    for (int i = 0; i < 8; i++) {
        int row = warp * 8 + i;
        float s = 0.f, t = 0.f;
#pragma unroll
        for (int k = lane; k < 256; k += 32) {
            float w = Sh[row * 260 + k];
            s += w * a[k];
            t += w * a[k + 256];
        }
#pragma unroll
        for (int off = 16; off; off >>= 1) {
            s += __shfl_down_sync(0xffffffffu, s, off);
            t += __shfl_down_sync(0xffffffffu, t, off);
        }
        if (lane == 0) {
            g_s[grow + row]  = s;
            g_Qq[grow + row] = make_float2(expf(t), expf(0.2f * t));
        }
    }
}

// ---------------- attention: warp-specialized, single rendezvous per chunk ----------------

// build 32 fp16 attention weights for (row, cols half*32..+32); returns partial Z
__device__ __forceinline__ float build32(__half* Ab, const float2* qb, const int4* av,
                                         float P, float p, int row, int half) {
    float z = 0.f;
    __align__(16) __half h[32];
#pragma unroll
    for (int q = 0; q < 8; q++) {
        int4 a = av[q];
        float2 q0 = qb[q * 4 + 0], q1 = qb[q * 4 + 1];
        float2 q2 = qb[q * 4 + 2], q3 = qb[q * 4 + 3];
        // exp(leaky(s+t)) = max(e^s e^t, e^{0.2s} e^{0.2t})
        float v0 = fmaxf(P * q0.x, p * q0.y); v0 = a.x ? v0 : 0.f;
        float v1 = fmaxf(P * q1.x, p * q1.y); v1 = a.y ? v1 : 0.f;
        float v2 = fmaxf(P * q2.x, p * q2.y); v2 = a.z ? v2 : 0.f;
        float v3 = fmaxf(P * q3.x, p * q3.y); v3 = a.w ? v3 : 0.f;
        z += (v0 + v1) + (v2 + v3);
        h[q * 4 + 0] = __float2half(v0);
        h[q * 4 + 1] = __float2half(v1);
        h[q * 4 + 2] = __float2half(v2);
        h[q * 4 + 3] = __float2half(v3);
    }
    uint4* d = (uint4*)(Ab + row * 72 + half * 32);
    d[0] = *(const uint4*)&h[0];
    d[1] = *(const uint4*)&h[8];
    d[2] = *(const uint4*)&h[16];
    d[3] = *(const uint4*)&h[24];
    return z;
}

// issue B(c) -> slot c%3 and Q(c+2) -> ring slot (c+2)&3
__device__ __forceinline__ void issueB(char* smem, int c, int ptid, float2* Qbase) {
    const char* bs = (const char*)g_Bh + (size_t)c * 32768;
    char* bd = smem + OFF_B + (c % 3) * B_BUF;
#pragma unroll
    for (int i = 0; i < 16; i++) {
        int idx = ptid + i * 128;
        int r = idx >> 5, sg = idx & 31;
        cpa16(bd + r * 528 + sg * 16, bs + (size_t)r * 512 + sg * 16);
    }
    if (ptid < 32 && c + 2 < NCHUNK)
        cpa16((char*)Qbase + ((c + 2) & 3) * 512 + ptid * 16,
              (const char*)g_Qq + (size_t)(c + 2) * 512 + ptid * 16);
    CP_COMMIT();
}

__device__ __forceinline__ void prod_iter(int c, char* smem, const int* aptr,
                                          const int4* bld, int4* pre,
                                          int ptid, int prow, int phalf,
                                          float P, float p, float& zacc,
                                          float* Zs, float2* Qbase) {
    // issue B(c+1) first: max flight time; slot (c+1)%3 free since consumer passed chunk c-2
    if (c + 1 < NCHUNK) {
        issueB(smem, c + 1, ptid, Qbase);
#pragma unroll
        for (int q = 0; q < 8; q++)
            pre[q] = ((const int4*)(aptr + (c + 1) * 64))[q];   // prefetch adj(c+1)
        asm volatile("cp.async.wait_group 1;" ::: "memory");     // B(c), Q(c+2) landed
    } else {
        asm volatile("cp.async.wait_group 0;" ::: "memory");
    }
    // build A(c) into slot c%3 (overlaps consumer MMA of chunk c-1)
    zacc += build32((__half*)(smem + (c % 3) * A_BUF),
                    Qbase + (c & 3) * 64 + phalf * 32, bld, P, p, prow, phalf);
    if (c == NCHUNK - 1) {
        float z = zacc;
        z += __shfl_xor_sync(0xffffffffu, z, 1);
        if (phalf == 0) Zs[prow] = (z > 0.f) ? 1.f / z : 0.f;
    }
    // rendezvous: fences producer STS (bar.sync drains STS); provides ring backpressure
    bar_sync(1, 384);
}

__global__ __launch_bounds__(384, 1) void attn_kernel(const int* __restrict__ adj,
                                                      float* __restrict__ out) {
    extern __shared__ __align__(16) char smem[];
    int tid  = threadIdx.x;
    int warp = tid >> 5;
    int grow = blockIdx.x * M_CTA;

    if (warp >= 8) {
        // ======================= PRODUCERS (warps 8-11) =======================
        int ptid  = tid - 256;          // 0..127
        int prow  = ptid >> 1;          // 0..63
        int phalf = ptid & 1;           // 32-col half
        float2* Qbase = (float2*)(smem + OFF_Q);
        float*  Zs    = (float*)(smem + OFF_Z);

        // preamble group: B(0) -> slot0, Q(0),Q(1),Q(2)
        {
            const char* bs = (const char*)g_Bh;
            char* bd = smem + OFF_B;
#pragma unroll
            for (int i = 0; i < 16; i++) {
                int idx = ptid + i * 128;
                int r = idx >> 5, sg = idx & 31;
                cpa16(bd + r * 528 + sg * 16, bs + (size_t)r * 512 + sg * 16);
            }
            if (ptid < 32) {
                cpa16((char*)Qbase + ptid * 16,        (const char*)g_Qq + ptid * 16);
                cpa16((char*)Qbase + 512 + ptid * 16,  (const char*)g_Qq + 512 + ptid * 16);
                cpa16((char*)Qbase + 1024 + ptid * 16, (const char*)g_Qq + 1024 + ptid * 16);
            }
            CP_COMMIT();
        }

        const int* aptr = adj + (size_t)(grow + prow) * N_NODES + phalf * 32;
        int4 av[8], av2[8];
#pragma unroll
        for (int q = 0; q < 8; q++) av[q] = ((const int4*)aptr)[q];   // adj(0)

        float s = g_s[grow + prow];
        float P = expf(s), p = expf(0.2f * s);
        float zacc = 0.f;

        asm volatile("cp.async.wait_group 0;" ::: "memory");   // B(0), Q(0..2)
        bar_sync(8, 128);                                       // producer-local visibility

        for (int c = 0; c < NCHUNK; c += 2) {
            prod_iter(c,     smem, aptr, av,  av2, ptid, prow, phalf, P, p, zacc, Zs, Qbase);
            prod_iter(c + 1, smem, aptr, av2, av,  ptid, prow, phalf, P, p, zacc, Zs, Qbase);
        }
        // producers exit; consumers run epilogue on their own barrier
    } else {
        // ======================= CONSUMERS (warps 0-7) =======================
        int m0 = (warp & 1) * 32;
        int n0 = (warp >> 1) * 64;

        wmma::fragment<wmma::accumulator, 16, 16, 16, float> acc[2][4];
#pragma unroll
        for (int mi = 0; mi < 2; mi++)
#pragma unroll
            for (int ni = 0; ni < 4; ni++) wmma::fill_fragment(acc[mi][ni], 0.f);

        for (int c = 0; c < NCHUNK; c++) {
            bar_sync(1, 384);                                  // rendezvous: chunk c ready
            const __half* Ab = (const __half*)(smem + (c % 3) * A_BUF);
            const __half* Bb = (const __half*)(smem + OFF_B + (c % 3) * B_BUF);
#pragma unroll
            for (int kk = 0; kk < 4; kk++) {
                wmma::fragment<wmma::matrix_a, 16, 16, 16, __half, wmma::row_major> af0, af1;
                wmma::load_matrix_sync(af0, Ab + (m0)      * 72 + kk * 16, 72);
                wmma::load_matrix_sync(af1, Ab + (m0 + 16) * 72 + kk * 16, 72);
#pragma unroll
                for (int ni = 0; ni < 4; ni++) {
                    wmma::fragment<wmma::matrix_b, 16, 16, 16, __half, wmma::row_major> bf;
                    wmma::load_matrix_sync(bf, Bb + kk * 16 * 264 + n0 + ni * 16, 264);
                    wmma::mma_sync(acc[0][ni], af0, bf, acc[0][ni]);
                    wmma::mma_sync(acc[1][ni], af1, bf, acc[1][ni]);
                }
            }
        }

        // ---- epilogue: out = elu( numerator / Z ) ----
        bar_sync(7, 256);                                      // consumers drained
        float* Sh = (float*)smem;                              // 64 x 260 fp32 overlay
#pragma unroll
        for (int mi = 0; mi < 2; mi++)
#pragma unroll
            for (int ni = 0; ni < 4; ni++)
                wmma::store_matrix_sync(Sh + (m0 + mi * 16) * 260 + n0 + ni * 16,
                                        acc[mi][ni], 260, wmma::mem_row_major);
        bar_sync(7, 256);
        float* Zsf = (float*)(smem + OFF_Z);
#pragma unroll 4
        for (int r = 0; r < 64; r++) {
            float val = Sh[r * 260 + tid] * Zsf[r];
            out[(size_t)(grow + r) * D_OUT + tid] = (val > 0.f) ? val : expm1f(val);
        }
    }
}

// ---------------- launch ----------------
extern "C" void kernel_launch(void* const* d_in, const int* in_sizes, int n_in,
                              void* d_out, int out_size) {
    const float* input  = nullptr;
    const int*   adj    = nullptr;
    const float* weight = nullptr;
    const float* a      = nullptr;
    for (int i = 0; i < n_in; i++) {
        switch (in_sizes[i]) {
            case N_NODES * D_IN:    input  = (const float*)d_in[i]; break;
            case 67108864:          adj    = (const int*)d_in[i];   break;
            case D_IN * D_OUT:      weight = (const float*)d_in[i]; break;
            case 2 * D_OUT:         a      = (const float*)d_in[i]; break;
        }
    }

    cudaFuncSetAttribute(gemm_wh_kernel, cudaFuncAttributeMaxDynamicSharedMemorySize, SMEM_GEMM);
    cudaFuncSetAttribute(attn_kernel,    cudaFuncAttributeMaxDynamicSharedMemorySize, SMEM_ATTN);

    __half* w_h;  cudaGetSymbolAddress((void**)&w_h, g_w_h);

    f2h_kernel<<<512, 256>>>(weight, w_h, D_IN * D_OUT);
    gemm_wh_kernel<<<N_NODES / 64, 256, SMEM_GEMM>>>(input, a);
    attn_kernel<<<N_NODES / M_CTA, 384, SMEM_ATTN>>>(adj, (float*)d_out);
}